// round 1
// baseline (speedup 1.0000x reference)
#include <cuda_runtime.h>

#define N_ATOMS 100000
#define N_PAIRS 1600000
#define DA 75
#define DP 14
#define DAGG 32
#define DAO 50
#define DPO 50
#define TC 24

// Scratch (allocation-free rule: __device__ globals)
__device__ float g_Tpa[N_ATOMS * DAGG];   // atom @ W_pa[14:89]      (12.8 MB)
__device__ float g_Tap[N_ATOMS * DPO];    // atom @ W_ap[14:89]      (20 MB)
__device__ float g_Asum[N_ATOMS * DAGG];  // segment_sum accumulator (12.8 MB)

// ---------------------------------------------------------------------------
// Kernel A: per-atom precompute T_pa (32 ch) + T_ap (50 ch), zero Asum.
// 32 atoms per block, shared-staged X and combined 75x82 weight (padded to 96).
// ---------------------------------------------------------------------------
__global__ __launch_bounds__(256) void atom_pre_kernel(
    const float* __restrict__ A,
    const float* __restrict__ Wpa,   // [89,32]
    const float* __restrict__ Wap)   // [89,50]
{
    __shared__ float sW[75 * 96];
    __shared__ float sX[32 * 75];
    int tid = threadIdx.x;

    for (int idx = tid; idx < 75 * 96; idx += 256) {
        int k = idx / 96, c = idx % 96;
        float v = 0.f;
        if (c < 32)      v = Wpa[(14 + k) * 32 + c];
        else if (c < 82) v = Wap[(14 + k) * 50 + (c - 32)];
        sW[idx] = v;
    }
    int base = blockIdx.x * 32;   // 100000 = 3125*32 exactly
    for (int idx = tid; idx < 32 * 75; idx += 256)
        sX[idx] = A[base * 75 + idx];   // idx = a*75+k, contiguous
    __syncthreads();

    int lane = tid & 31, wy = tid >> 5;
    int a0 = wy * 4;   // 8 warps * 4 atoms = 32
    float acc[4][3];
#pragma unroll
    for (int a = 0; a < 4; a++) { acc[a][0] = acc[a][1] = acc[a][2] = 0.f; }

#pragma unroll 5
    for (int k = 0; k < 75; k++) {
        float w0 = sW[k * 96 + lane];
        float w1 = sW[k * 96 + lane + 32];
        float w2 = sW[k * 96 + lane + 64];
#pragma unroll
        for (int a = 0; a < 4; a++) {
            float x = sX[(a0 + a) * 75 + k];   // warp-uniform broadcast
            acc[a][0] = fmaf(x, w0, acc[a][0]);
            acc[a][1] = fmaf(x, w1, acc[a][1]);
            acc[a][2] = fmaf(x, w2, acc[a][2]);
        }
    }
#pragma unroll
    for (int a = 0; a < 4; a++) {
        int ga = base + a0 + a;
        g_Tpa[ga * 32 + lane] = acc[a][0];                 // combined col lane      -> T_pa[lane]
        g_Tap[ga * 50 + lane] = acc[a][1];                 // combined col lane+32   -> T_ap[lane]
        if (lane < 18)
            g_Tap[ga * 50 + 32 + lane] = acc[a][2];        // combined col lane+64   -> T_ap[lane+32]
        g_Asum[ga * 32 + lane] = 0.f;
    }
}

// ---------------------------------------------------------------------------
// Pair kernel: warp-per-pair, weights in registers, grid-stride over pairs.
//   A_paj = relu(pf@Wpa[0:14] + T_pa[j] + b_pa)          -> atomic into Asum[i]
//   pair_hidden = relu(relu(pf@Wap[0:14] + T_ap[i]+T_ap[j] + b_ap)
//                      + relu(pf@Wpp + b_pp))
// ---------------------------------------------------------------------------
__global__ __launch_bounds__(256, 2) void pair_kernel(
    const float* __restrict__ pf,
    const int2*  __restrict__ a2p,
    const float* __restrict__ Wpa, const float* __restrict__ bpa,
    const float* __restrict__ Wap, const float* __restrict__ bap,
    const float* __restrict__ Wpp, const float* __restrict__ bpp,
    float* __restrict__ pair_out)
{
    int lane   = threadIdx.x & 31;
    int warp   = blockIdx.x * (blockDim.x >> 5) + (threadIdx.x >> 5);
    int nwarps = gridDim.x * (blockDim.x >> 5);
    int c1  = lane + 32;
    int c1c = (c1 < 50) ? c1 : 49;   // clamped (dup col 49, stores guarded)
    bool has1 = (lane < 18);

    float wpa[14], wap0[14], wap1[14], wpp0[14], wpp1[14];
#pragma unroll
    for (int k = 0; k < 14; k++) {
        wpa[k]  = Wpa[k * 32 + lane];
        wap0[k] = Wap[k * 50 + lane];
        wap1[k] = Wap[k * 50 + c1c];
        wpp0[k] = Wpp[k * 50 + lane];
        wpp1[k] = Wpp[k * 50 + c1c];
    }
    float bpa_l = bpa[lane];
    float bap0 = bap[lane], bap1 = bap[c1c];
    float bpp0 = bpp[lane], bpp1 = bpp[c1c];

    for (int p = warp; p < N_PAIRS; p += nwarps) {
        int2 ij = a2p[p];
        int i = ij.x, j = ij.y;
        float pfv = (lane < 14) ? pf[p * 14 + lane] : 0.f;

        float accA  = bpa_l + g_Tpa[j * 32 + lane];
        float accP0 = bap0 + g_Tap[i * 50 + lane] + g_Tap[j * 50 + lane];
        float accP1 = has1 ? (bap1 + g_Tap[i * 50 + c1] + g_Tap[j * 50 + c1]) : 0.f;
        float accQ0 = bpp0, accQ1 = bpp1;

#pragma unroll
        for (int k = 0; k < 14; k++) {
            float x = __shfl_sync(0xffffffffu, pfv, k);
            accA  = fmaf(x, wpa[k],  accA);
            accP0 = fmaf(x, wap0[k], accP0);
            accP1 = fmaf(x, wap1[k], accP1);
            accQ0 = fmaf(x, wpp0[k], accQ0);
            accQ1 = fmaf(x, wpp1[k], accQ1);
        }

        atomicAdd(&g_Asum[i * 32 + lane], fmaxf(accA, 0.f));

        float h0 = fmaxf(accP0, 0.f) + fmaxf(accQ0, 0.f);  // already >= 0
        pair_out[(size_t)p * 50 + lane] = h0;
        if (has1)
            pair_out[(size_t)p * 50 + c1] = fmaxf(accP1, 0.f) + fmaxf(accQ1, 0.f);
    }
}

// ---------------------------------------------------------------------------
// Kernel C: atom output.
//   atom_hidden = relu([atom,Asum]@W_ao + b_ao) + relu(atom@W_aa + b_aa)
// 24 atoms per block (shared budget), 3 atoms/warp x channels {lane, lane+32}.
// ---------------------------------------------------------------------------
__global__ __launch_bounds__(256) void atom_out_kernel(
    const float* __restrict__ A,
    const float* __restrict__ Wao, const float* __restrict__ bao,   // [107,50]
    const float* __restrict__ Waa, const float* __restrict__ baa,   // [75,50]
    float* __restrict__ out)
{
    __shared__ float sX[TC * 107];
    __shared__ float sWao[107 * 50];
    __shared__ float sWaa[75 * 50];
    int tid = threadIdx.x;

    for (int idx = tid; idx < 107 * 50; idx += 256) sWao[idx] = Wao[idx];
    for (int idx = tid; idx < 75 * 50;  idx += 256) sWaa[idx] = Waa[idx];

    int base = blockIdx.x * TC;
    for (int idx = tid; idx < TC * 107; idx += 256) {
        int a = idx / 107, k = idx % 107;
        int ga = base + a;
        float v = 0.f;
        if (ga < N_ATOMS)
            v = (k < 75) ? A[ga * 75 + k] : g_Asum[ga * 32 + (k - 75)];
        sX[idx] = v;
    }
    __syncthreads();

    int lane = tid & 31, wy = tid >> 5;
    int a0 = wy * 3;                       // 8 warps * 3 atoms = 24
    int c1c = (lane + 32 < 50) ? lane + 32 : 49;

    float ao[3][2], aa[3][2];
#pragma unroll
    for (int a = 0; a < 3; a++) { ao[a][0] = ao[a][1] = aa[a][0] = aa[a][1] = 0.f; }

    for (int k = 0; k < 75; k++) {
        float w0 = sWao[k * 50 + lane], w1 = sWao[k * 50 + c1c];
        float v0 = sWaa[k * 50 + lane], v1 = sWaa[k * 50 + c1c];
#pragma unroll
        for (int a = 0; a < 3; a++) {
            float x = sX[(a0 + a) * 107 + k];
            ao[a][0] = fmaf(x, w0, ao[a][0]);
            ao[a][1] = fmaf(x, w1, ao[a][1]);
            aa[a][0] = fmaf(x, v0, aa[a][0]);
            aa[a][1] = fmaf(x, v1, aa[a][1]);
        }
    }
    for (int k = 75; k < 107; k++) {
        float w0 = sWao[k * 50 + lane], w1 = sWao[k * 50 + c1c];
#pragma unroll
        for (int a = 0; a < 3; a++) {
            float x = sX[(a0 + a) * 107 + k];
            ao[a][0] = fmaf(x, w0, ao[a][0]);
            ao[a][1] = fmaf(x, w1, ao[a][1]);
        }
    }

    float b_ao0 = bao[lane], b_ao1 = bao[c1c];
    float b_aa0 = baa[lane], b_aa1 = baa[c1c];
#pragma unroll
    for (int a = 0; a < 3; a++) {
        int ga = base + a0 + a;
        if (ga < N_ATOMS) {
            out[(size_t)ga * 50 + lane] =
                fmaxf(ao[a][0] + b_ao0, 0.f) + fmaxf(aa[a][0] + b_aa0, 0.f);
            if (lane < 18)
                out[(size_t)ga * 50 + lane + 32] =
                    fmaxf(ao[a][1] + b_ao1, 0.f) + fmaxf(aa[a][1] + b_aa1, 0.f);
        }
    }
}

// ---------------------------------------------------------------------------
extern "C" void kernel_launch(void* const* d_in, const int* in_sizes, int n_in,
                              void* d_out, int out_size) {
    const float* atom_features = (const float*)d_in[0];
    const float* pair_features = (const float*)d_in[1];
    const float* W_pa = (const float*)d_in[2];
    const float* b_pa = (const float*)d_in[3];
    const float* W_ao = (const float*)d_in[4];
    const float* b_ao = (const float*)d_in[5];
    const float* W_aa = (const float*)d_in[6];
    const float* b_aa = (const float*)d_in[7];
    const float* W_ap = (const float*)d_in[8];
    const float* b_ap = (const float*)d_in[9];
    const float* W_pp = (const float*)d_in[10];
    const float* b_pp = (const float*)d_in[11];
    // d_in[12] = pair_split (duplicate of atom_to_pair[:,0], unused)
    const int2* atom_to_pair = (const int2*)d_in[13];

    float* out = (float*)d_out;
    float* atom_out_ptr = out;                              // [100000, 50]
    float* pair_out_ptr = out + (size_t)N_ATOMS * DAO;      // [1600000, 50]

    atom_pre_kernel<<<N_ATOMS / 32, 256>>>(atom_features, W_pa, W_ap);
    pair_kernel<<<2048, 256>>>(pair_features, atom_to_pair,
                               W_pa, b_pa, W_ap, b_ap, W_pp, b_pp, pair_out_ptr);
    atom_out_kernel<<<(N_ATOMS + TC - 1) / TC, 256>>>(
        atom_features, W_ao, b_ao, W_aa, b_aa, atom_out_ptr);
}

// round 5
// speedup vs baseline: 1.3493x; 1.3493x over previous
#include <cuda_runtime.h>

#define N_ATOMS 100000
#define N_PAIRS 1600000
#define DA 75
#define DP 14
#define DAGG 32
#define DAO 50
#define DPO 50
#define TC 24
#define FULLMASK 0xffffffffu

typedef unsigned long long ull;

// ---- packed f32x2 helpers (sm_10x FFMA2 path, PTX-only) --------------------
__device__ __forceinline__ ull pack2(float x, float y) {
    ull r; asm("mov.b64 %0,{%1,%2};" : "=l"(r) : "f"(x), "f"(y)); return r;
}
__device__ __forceinline__ ull fma2(ull a, ull b, ull c) {
    ull d; asm("fma.rn.f32x2 %0,%1,%2,%3;" : "=l"(d) : "l"(a), "l"(b), "l"(c)); return d;
}
__device__ __forceinline__ ull add2(ull a, ull b) {
    ull d; asm("add.rn.f32x2 %0,%1,%2;" : "=l"(d) : "l"(a), "l"(b)); return d;
}
__device__ __forceinline__ void unpack2(ull v, float& x, float& y) {
    asm("mov.b64 {%0,%1},%2;" : "=f"(x), "=f"(y) : "l"(v));
}

// Scratch (allocation-free rule: __device__ globals)
__device__ float g_Tpa[N_ATOMS * DAGG];   // atom @ W_pa[14:89]      (12.8 MB)
__device__ float g_Tap[N_ATOMS * DPO];    // atom @ W_ap[14:89]      (20 MB)
__device__ float g_Asum[N_ATOMS * DAGG];  // segment_sum accumulator (12.8 MB)

// ---------------------------------------------------------------------------
// Kernel A: per-atom precompute T_pa (32 ch) + T_ap (50 ch), zero Asum.
// ---------------------------------------------------------------------------
__global__ __launch_bounds__(256) void atom_pre_kernel(
    const float* __restrict__ A,
    const float* __restrict__ Wpa,   // [89,32]
    const float* __restrict__ Wap)   // [89,50]
{
    __shared__ float sW[75 * 96];
    __shared__ float sX[32 * 75];
    int tid = threadIdx.x;

    for (int idx = tid; idx < 75 * 96; idx += 256) {
        int k = idx / 96, c = idx % 96;
        float v = 0.f;
        if (c < 32)      v = Wpa[(14 + k) * 32 + c];
        else if (c < 82) v = Wap[(14 + k) * 50 + (c - 32)];
        sW[idx] = v;
    }
    int base = blockIdx.x * 32;   // 100000 = 3125*32 exactly
    for (int idx = tid; idx < 32 * 75; idx += 256)
        sX[idx] = A[base * 75 + idx];
    __syncthreads();

    int lane = tid & 31, wy = tid >> 5;
    int a0 = wy * 4;
    float acc[4][3];
#pragma unroll
    for (int a = 0; a < 4; a++) { acc[a][0] = acc[a][1] = acc[a][2] = 0.f; }

#pragma unroll 5
    for (int k = 0; k < 75; k++) {
        float w0 = sW[k * 96 + lane];
        float w1 = sW[k * 96 + lane + 32];
        float w2 = sW[k * 96 + lane + 64];
#pragma unroll
        for (int a = 0; a < 4; a++) {
            float x = sX[(a0 + a) * 75 + k];
            acc[a][0] = fmaf(x, w0, acc[a][0]);
            acc[a][1] = fmaf(x, w1, acc[a][1]);
            acc[a][2] = fmaf(x, w2, acc[a][2]);
        }
    }
#pragma unroll
    for (int a = 0; a < 4; a++) {
        int ga = base + a0 + a;
        g_Tpa[ga * 32 + lane] = acc[a][0];
        g_Tap[ga * 50 + lane] = acc[a][1];
        if (lane < 18)
            g_Tap[ga * 50 + 32 + lane] = acc[a][2];
        g_Asum[ga * 32 + lane] = 0.f;
    }
}

// ---------------------------------------------------------------------------
// Pair kernel v2: warp-per-pair over a CONTIGUOUS chunk, f32x2 packed math,
// run-length-accumulated segment sum (pairs are sorted by i).
//   lane l < 16 : A channels {2l, 2l+1}   (32 ch)
//   lane l < 25 : P/Q channels {2l, 2l+1} (50 ch)
// ---------------------------------------------------------------------------
__global__ __launch_bounds__(256, 2) void pair_kernel(
    const float* __restrict__ pf,
    const int2*  __restrict__ a2p,
    const float* __restrict__ Wpa, const float* __restrict__ bpa,
    const float* __restrict__ Wap, const float* __restrict__ bap,
    const float* __restrict__ Wpp, const float* __restrict__ bpp,
    float* __restrict__ pair_out)
{
    int lane = threadIdx.x & 31;
    int warp = blockIdx.x * 8 + (threadIdx.x >> 5);
    int nw   = gridDim.x * 8;
    int chunk = (N_PAIRS + nw - 1) / nw;
    int p0 = warp * chunk;
    int p1 = min(p0 + chunk, N_PAIRS);

    int cA = 2 * (lane & 15);                   // lanes 16-31 duplicate (stores guarded)
    int cP = 2 * (lane < 25 ? lane : 24);       // lanes 25-31 duplicate (stores guarded)
    bool laneA = lane < 16, laneP = lane < 25;

    ull wpa2[14], wap2[14], wpp2[14];
#pragma unroll
    for (int k = 0; k < 14; k++) {
        wpa2[k] = *(const ull*)(Wpa + k * 32 + cA);
        wap2[k] = *(const ull*)(Wap + k * 50 + cP);
        wpp2[k] = *(const ull*)(Wpp + k * 50 + cP);
    }
    ull bpa2 = *(const ull*)(bpa + cA);
    ull bap2 = *(const ull*)(bap + cP);
    ull bpp2 = *(const ull*)(bpp + cP);

    int cur_i = -1;
    float sA0 = 0.f, sA1 = 0.f;
    ull tap_i = 0;

#pragma unroll 1
    for (int p = p0; p < p1; ++p) {
        int2 ij = a2p[p];          // warp-uniform
        int j = ij.y;
        if (ij.x != cur_i) {       // warp-uniform branch
            if (cur_i >= 0 && laneA) {
                atomicAdd(&g_Asum[cur_i * 32 + cA],     sA0);
                atomicAdd(&g_Asum[cur_i * 32 + cA + 1], sA1);
            }
            cur_i = ij.x;
            sA0 = 0.f; sA1 = 0.f;
            tap_i = *(const ull*)(g_Tap + (size_t)cur_i * 50 + cP);
        }

        float pfv = (lane < 14) ? pf[p * 14 + lane] : 0.f;

        ull accA = add2(bpa2, *(const ull*)(g_Tpa + (size_t)j * 32 + cA));
        ull accP = add2(add2(bap2, tap_i), *(const ull*)(g_Tap + (size_t)j * 50 + cP));
        ull accQ = bpp2;

#pragma unroll
        for (int k = 0; k < 14; k++) {
            float x = __shfl_sync(FULLMASK, pfv, k);
            ull xx = pack2(x, x);
            accA = fma2(xx, wpa2[k], accA);
            accP = fma2(xx, wap2[k], accP);
            accQ = fma2(xx, wpp2[k], accQ);
        }

        float a0, a1, pv0, pv1, q0, q1;
        unpack2(accA, a0, a1);
        unpack2(accP, pv0, pv1);
        unpack2(accQ, q0, q1);
        sA0 += fmaxf(a0, 0.f);
        sA1 += fmaxf(a1, 0.f);
        if (laneP) {
            float2 h;
            h.x = fmaxf(pv0, 0.f) + fmaxf(q0, 0.f);
            h.y = fmaxf(pv1, 0.f) + fmaxf(q1, 0.f);
            *(float2*)(pair_out + (size_t)p * 50 + cP) = h;
        }
    }
    if (cur_i >= 0 && laneA) {
        atomicAdd(&g_Asum[cur_i * 32 + cA],     sA0);
        atomicAdd(&g_Asum[cur_i * 32 + cA + 1], sA1);
    }
}

// ---------------------------------------------------------------------------
// Kernel C: atom output.
// ---------------------------------------------------------------------------
__global__ __launch_bounds__(256) void atom_out_kernel(
    const float* __restrict__ A,
    const float* __restrict__ Wao, const float* __restrict__ bao,   // [107,50]
    const float* __restrict__ Waa, const float* __restrict__ baa,   // [75,50]
    float* __restrict__ out)
{
    __shared__ float sX[TC * 107];
    __shared__ float sWao[107 * 50];
    __shared__ float sWaa[75 * 50];
    int tid = threadIdx.x;

    for (int idx = tid; idx < 107 * 50; idx += 256) sWao[idx] = Wao[idx];
    for (int idx = tid; idx < 75 * 50;  idx += 256) sWaa[idx] = Waa[idx];

    int base = blockIdx.x * TC;
    for (int idx = tid; idx < TC * 107; idx += 256) {
        int a = idx / 107, k = idx % 107;
        int ga = base + a;
        float v = 0.f;
        if (ga < N_ATOMS)
            v = (k < 75) ? A[ga * 75 + k] : g_Asum[ga * 32 + (k - 75)];
        sX[idx] = v;
    }
    __syncthreads();

    int lane = tid & 31, wy = tid >> 5;
    int a0 = wy * 3;
    int c1c = (lane + 32 < 50) ? lane + 32 : 49;

    float ao[3][2], aa[3][2];
#pragma unroll
    for (int a = 0; a < 3; a++) { ao[a][0] = ao[a][1] = aa[a][0] = aa[a][1] = 0.f; }

    for (int k = 0; k < 75; k++) {
        float w0 = sWao[k * 50 + lane], w1 = sWao[k * 50 + c1c];
        float v0 = sWaa[k * 50 + lane], v1 = sWaa[k * 50 + c1c];
#pragma unroll
        for (int a = 0; a < 3; a++) {
            float x = sX[(a0 + a) * 107 + k];
            ao[a][0] = fmaf(x, w0, ao[a][0]);
            ao[a][1] = fmaf(x, w1, ao[a][1]);
            aa[a][0] = fmaf(x, v0, aa[a][0]);
            aa[a][1] = fmaf(x, v1, aa[a][1]);
        }
    }
    for (int k = 75; k < 107; k++) {
        float w0 = sWao[k * 50 + lane], w1 = sWao[k * 50 + c1c];
#pragma unroll
        for (int a = 0; a < 3; a++) {
            float x = sX[(a0 + a) * 107 + k];
            ao[a][0] = fmaf(x, w0, ao[a][0]);
            ao[a][1] = fmaf(x, w1, ao[a][1]);
        }
    }

    float b_ao0 = bao[lane], b_ao1 = bao[c1c];
    float b_aa0 = baa[lane], b_aa1 = baa[c1c];
#pragma unroll
    for (int a = 0; a < 3; a++) {
        int ga = base + a0 + a;
        if (ga < N_ATOMS) {
            out[(size_t)ga * 50 + lane] =
                fmaxf(ao[a][0] + b_ao0, 0.f) + fmaxf(aa[a][0] + b_aa0, 0.f);
            if (lane < 18)
                out[(size_t)ga * 50 + lane + 32] =
                    fmaxf(ao[a][1] + b_ao1, 0.f) + fmaxf(aa[a][1] + b_aa1, 0.f);
        }
    }
}

// ---------------------------------------------------------------------------
extern "C" void kernel_launch(void* const* d_in, const int* in_sizes, int n_in,
                              void* d_out, int out_size) {
    const float* atom_features = (const float*)d_in[0];
    const float* pair_features = (const float*)d_in[1];
    const float* W_pa = (const float*)d_in[2];
    const float* b_pa = (const float*)d_in[3];
    const float* W_ao = (const float*)d_in[4];
    const float* b_ao = (const float*)d_in[5];
    const float* W_aa = (const float*)d_in[6];
    const float* b_aa = (const float*)d_in[7];
    const float* W_ap = (const float*)d_in[8];
    const float* b_ap = (const float*)d_in[9];
    const float* W_pp = (const float*)d_in[10];
    const float* b_pp = (const float*)d_in[11];
    // d_in[12] = pair_split (duplicate of atom_to_pair[:,0], unused)
    const int2* atom_to_pair = (const int2*)d_in[13];

    float* out = (float*)d_out;
    float* atom_out_ptr = out;                              // [100000, 50]
    float* pair_out_ptr = out + (size_t)N_ATOMS * DAO;      // [1600000, 50]

    atom_pre_kernel<<<N_ATOMS / 32, 256>>>(atom_features, W_pa, W_ap);
    pair_kernel<<<304, 256>>>(pair_features, atom_to_pair,
                              W_pa, b_pa, W_ap, b_ap, W_pp, b_pp, pair_out_ptr);
    atom_out_kernel<<<(N_ATOMS + TC - 1) / TC, 256>>>(
        atom_features, W_ao, b_ao, W_aa, b_aa, atom_out_ptr);
}